// round 10
// baseline (speedup 1.0000x reference)
#include <cuda_runtime.h>
#include <math_constants.h>

// ---------------- problem constants ----------------
#define B_   32
#define C_   128
#define N_   4096
#define M_   512
#define L_   6
#define EPSI 1e-5f

// ---------------- scratch (device globals; no runtime alloc) ----------------
__device__ float g_S [(size_t)B_ * M_ * N_];   // 256 MB: logits / softmax buffer
__device__ float g_h [(size_t)B_ * M_ * C_];   // 8 MB: pooled features / residual stream
__device__ float g_y [(size_t)B_ * M_ * C_];   // 8 MB: filter layer pre-BN output
__device__ float g_mu  [M_];
__device__ float g_istd[M_];

// ---------------- warp/block reduce helpers ----------------
__device__ __forceinline__ float warp_sum(float v) {
    #pragma unroll
    for (int o = 16; o > 0; o >>= 1) v += __shfl_xor_sync(0xffffffffu, v, o);
    return v;
}
__device__ __forceinline__ float warp_max(float v) {
    #pragma unroll
    for (int o = 16; o > 0; o >>= 1) v = fmaxf(v, __shfl_xor_sync(0xffffffffu, v, o));
    return v;
}

// ---------------- generic tiled fp32 GEMM: C[m,n] = sum_k A[m,k]*B[k,n] (+bias[m]) ----
// 64x64 tile, K-step 16, 256 threads, 4x4 micro-tile per thread.
// A_KCONTIG: global A is contiguous along k (lda_k==1) -> load k-fast.
// B_NCONTIG: global B is contiguous along n (ldb_n==1) -> load n-fast.
template<bool A_KCONTIG, bool B_NCONTIG, bool BIAS>
__global__ __launch_bounds__(256)
void gemm64(const float* __restrict__ A, const float* __restrict__ B,
            float* __restrict__ C, const float* __restrict__ bias,
            int K,
            long a_batch, long b_batch, long c_batch,
            int lda_m, int lda_k, int ldb_k, int ldb_n, int ldc)
{
    __shared__ float As[16][64];
    __shared__ float Bs[16][64];

    const float* Ab = A + (long)blockIdx.z * a_batch;
    const float* Bb = B + (long)blockIdx.z * b_batch;
    float*       Cb = C + (long)blockIdx.z * c_batch;

    const int m0  = blockIdx.y * 64;
    const int n0  = blockIdx.x * 64;
    const int tid = threadIdx.x;
    const int tx  = tid & 15;   // n direction
    const int ty  = tid >> 4;   // m direction

    float acc[4][4] = {};

    for (int k0 = 0; k0 < K; k0 += 16) {
        #pragma unroll
        for (int i = 0; i < 4; i++) {
            int idx = tid + i * 256;
            int m, k;
            if (A_KCONTIG) { m = idx >> 4; k = idx & 15; }
            else           { k = idx >> 6; m = idx & 63; }
            As[k][m] = Ab[(long)(m0 + m) * lda_m + (long)(k0 + k) * lda_k];
        }
        #pragma unroll
        for (int i = 0; i < 4; i++) {
            int idx = tid + i * 256;
            int k, n;
            if (B_NCONTIG) { k = idx >> 6; n = idx & 63; }
            else           { n = idx >> 4; k = idx & 15; }
            Bs[k][n] = Bb[(long)(k0 + k) * ldb_k + (long)(n0 + n) * ldb_n];
        }
        __syncthreads();
        #pragma unroll
        for (int kk = 0; kk < 16; kk++) {
            float4 av = *(const float4*)&As[kk][4 * ty];
            float4 bv = *(const float4*)&Bs[kk][4 * tx];
            float a[4] = {av.x, av.y, av.z, av.w};
            float b[4] = {bv.x, bv.y, bv.z, bv.w};
            #pragma unroll
            for (int i = 0; i < 4; i++)
                #pragma unroll
                for (int j = 0; j < 4; j++)
                    acc[i][j] = fmaf(a[i], b[j], acc[i][j]);
        }
        __syncthreads();
    }

    #pragma unroll
    for (int i = 0; i < 4; i++) {
        int m = m0 + 4 * ty + i;
        float bval = BIAS ? bias[m] : 0.0f;
        float4 v;
        v.x = acc[i][0] + bval;
        v.y = acc[i][1] + bval;
        v.z = acc[i][2] + bval;
        v.w = acc[i][3] + bval;
        *(float4*)&Cb[(long)m * ldc + n0 + 4 * tx] = v;
    }
}

// ---------------- softmax over rows of length N_ (axis=2 of [B,M,N]) -----------
__global__ __launch_bounds__(256)
void softmax_rows(float* __restrict__ S)
{
    float* p = S + (long)blockIdx.x * N_;
    const int tid  = threadIdx.x;
    const int lane = tid & 31;
    const int wid  = tid >> 5;
    __shared__ float red[8];

    float v[16];
    float mx = -CUDART_INF_F;
    #pragma unroll
    for (int j = 0; j < 16; j++) { v[j] = p[tid + j * 256]; mx = fmaxf(mx, v[j]); }

    mx = warp_max(mx);
    if (lane == 0) red[wid] = mx;
    __syncthreads();
    #pragma unroll
    for (int i = 0; i < 8; i++) mx = fmaxf(mx, red[i]);

    float s = 0.f;
    #pragma unroll
    for (int j = 0; j < 16; j++) { v[j] = __expf(v[j] - mx); s += v[j]; }

    s = warp_sum(s);
    __syncthreads();
    if (lane == 0) red[wid] = s;
    __syncthreads();
    float tot = 0.f;
    #pragma unroll
    for (int i = 0; i < 8; i++) tot += red[i];
    float inv = 1.0f / tot;

    #pragma unroll
    for (int j = 0; j < 16; j++) p[tid + j * 256] = v[j] * inv;
}

// ---------------- softmax over m (axis=1 of [B,M,N], stride N_) -----------------
__global__ __launch_bounds__(256)
void softmax_cols(float* __restrict__ U)
{
    const int b = blockIdx.y;
    const int n = blockIdx.x * 256 + threadIdx.x;
    float* base = U + (long)b * M_ * N_ + n;

    float mx = -CUDART_INF_F, s = 0.f;
    #pragma unroll 4
    for (int m = 0; m < M_; m++) {
        float vv = base[(long)m * N_];
        float nm = fmaxf(mx, vv);
        s = s * __expf(mx - nm) + __expf(vv - nm);
        mx = nm;
    }
    float inv = 1.0f / s;
    #pragma unroll 4
    for (int m = 0; m < M_; m++) {
        long off = (long)m * N_;
        base[off] = __expf(base[off] - mx) * inv;
    }
}

// ---------------- BN stats per output channel o over (B, C) ---------------------
__global__ __launch_bounds__(256)
void bn_stats(const float* __restrict__ y, float* __restrict__ mu, float* __restrict__ istd)
{
    const int o = blockIdx.x;
    const int tid  = threadIdx.x;
    const int lane = tid & 31;
    const int wid  = tid >> 5;
    __shared__ float rs[8], rq[8];

    float s = 0.f, q = 0.f;
    for (int idx = tid; idx < B_ * C_; idx += 256) {
        int b = idx >> 7, c = idx & 127;
        float vv = y[(long)b * M_ * C_ + (long)o * C_ + c];
        s += vv; q += vv * vv;
    }
    s = warp_sum(s);
    q = warp_sum(q);
    if (lane == 0) { rs[wid] = s; rq[wid] = q; }
    __syncthreads();
    if (tid == 0) {
        float S = 0.f, Q = 0.f;
        #pragma unroll
        for (int i = 0; i < 8; i++) { S += rs[i]; Q += rq[i]; }
        float mean = S * (1.0f / (B_ * C_));
        float var  = Q * (1.0f / (B_ * C_)) - mean * mean;
        mu[o]   = mean;
        istd[o] = rsqrtf(var + EPSI);
    }
}

// ---------------- BN apply + residual + relu, updates h in place ----------------
__global__ __launch_bounds__(256)
void bn_apply(const float* __restrict__ y, float* __restrict__ h,
              const float* __restrict__ mu, const float* __restrict__ istd,
              const float* __restrict__ gamma, const float* __restrict__ beta)
{
    long i = (long)blockIdx.x * 256 + threadIdx.x;   // B*M*C = 2,097,152
    int o = (int)((i >> 7) & (M_ - 1));
    float yn = (y[i] - mu[o]) * istd[o] * gamma[o] + beta[o];
    h[i] = fmaxf(yn + h[i], 0.0f);
}

// ---------------- launch ---------------------------------------------------------
extern "C" void kernel_launch(void* const* d_in, const int* in_sizes, int n_in,
                              void* d_out, int out_size)
{
    const float* x        = (const float*)d_in[0];   // [B, C, N, 1]
    const float* W_pool   = (const float*)d_in[1];   // [M, C]
    const float* Wf       = (const float*)d_in[2];   // [L, M, M]
    const float* gamma    = (const float*)d_in[3];   // [L, M]
    const float* beta     = (const float*)d_in[4];   // [L, M]
    const float* W_unpool = (const float*)d_in[5];   // [M, C]
    const float* b_unpool = (const float*)d_in[6];   // [M]
    float*       out      = (float*)d_out;           // [B, C, N, 1]

    float *pS, *ph, *py, *pmu, *pistd;
    cudaGetSymbolAddress((void**)&pS,    g_S);
    cudaGetSymbolAddress((void**)&ph,    g_h);
    cudaGetSymbolAddress((void**)&py,    g_y);
    cudaGetSymbolAddress((void**)&pmu,   g_mu);
    cudaGetSymbolAddress((void**)&pistd, g_istd);

    const long MN = (long)M_ * N_;
    const long CN = (long)C_ * N_;
    const long MC = (long)M_ * C_;

    // 1) pool logits: S[b,m,n] = sum_c W_pool[m,c] * x[b,c,n]
    gemm64<true, true, false><<<dim3(N_ / 64, M_ / 64, B_), 256>>>(
        W_pool, x, pS, nullptr, C_,
        0, CN, MN, C_, 1, N_, 1, N_);

    // 2) softmax over n
    softmax_rows<<<B_ * M_, 256>>>(pS);

    // 3) pooled features: h[b,m,c] = sum_n S[b,m,n] * x[b,c,n]
    gemm64<true, false, false><<<dim3(C_ / 64, M_ / 64, B_), 256>>>(
        pS, x, ph, nullptr, N_,
        MN, CN, MC, N_, 1, 1, N_, C_);

    // 4) filtering layers
    for (int l = 0; l < L_; l++) {
        gemm64<true, true, false><<<dim3(C_ / 64, M_ / 64, B_), 256>>>(
            Wf + (long)l * M_ * M_, ph, py, nullptr, M_,
            0, MC, MC, M_, 1, C_, 1, C_);
        bn_stats<<<M_, 256>>>(py, pmu, pistd);
        bn_apply<<<(B_ * M_ * C_) / 256, 256>>>(py, ph, pmu, pistd,
                                                gamma + l * M_, beta + l * M_);
    }

    // 5) unpool logits: S[b,m,n] = sum_c W_unpool[m,c] * x[b,c,n] + b_unpool[m]
    gemm64<true, true, true><<<dim3(N_ / 64, M_ / 64, B_), 256>>>(
        W_unpool, x, pS, b_unpool, C_,
        0, CN, MN, C_, 1, N_, 1, N_);

    // 6) softmax over m
    softmax_cols<<<dim3(N_ / 256, B_), 256>>>(pS);

    // 7) output: out[b,c,n] = sum_m h[b,m,c] * S[b,m,n]
    gemm64<false, true, false><<<dim3(N_ / 64, C_ / 64, B_), 256>>>(
        ph, pS, out, nullptr, M_,
        MC, MN, CN, 1, C_, N_, 1, N_);
}

// round 11
// speedup vs baseline: 1.0052x; 1.0052x over previous
#include <cuda_runtime.h>
#include <math_constants.h>

// ---------------- problem constants ----------------
#define B_   32
#define C_   128
#define N_   4096
#define M_   512
#define L_   6
#define EPSI 1e-5f

// ---------------- scratch (device globals; no runtime alloc) ----------------
__device__ float g_S [(size_t)B_ * M_ * N_];   // 256 MB: logits / softmax buffer
__device__ float g_h [(size_t)B_ * M_ * C_];   // 8 MB: pooled features / residual stream
__device__ float g_y [(size_t)B_ * M_ * C_];   // 8 MB: filter layer pre-BN output
__device__ float g_mu  [M_];
__device__ float g_istd[M_];

// ---------------- warp/block reduce helpers ----------------
__device__ __forceinline__ float warp_sum(float v) {
    #pragma unroll
    for (int o = 16; o > 0; o >>= 1) v += __shfl_xor_sync(0xffffffffu, v, o);
    return v;
}
__device__ __forceinline__ float warp_max(float v) {
    #pragma unroll
    for (int o = 16; o > 0; o >>= 1) v = fmaxf(v, __shfl_xor_sync(0xffffffffu, v, o));
    return v;
}

// ---------------- generic tiled fp32 GEMM: C[m,n] = sum_k A[m,k]*B[k,n] (+bias[m]) ----
// 64x64 tile, K-step 16, 256 threads, 4x4 micro-tile per thread.
// A_KCONTIG: global A is contiguous along k (lda_k==1) -> load k-fast.
// B_NCONTIG: global B is contiguous along n (ldb_n==1) -> load n-fast.
template<bool A_KCONTIG, bool B_NCONTIG, bool BIAS>
__global__ __launch_bounds__(256)
void gemm64(const float* __restrict__ A, const float* __restrict__ B,
            float* __restrict__ C, const float* __restrict__ bias,
            int K,
            long a_batch, long b_batch, long c_batch,
            int lda_m, int lda_k, int ldb_k, int ldb_n, int ldc)
{
    __shared__ float As[16][64];
    __shared__ float Bs[16][64];

    const float* Ab = A + (long)blockIdx.z * a_batch;
    const float* Bb = B + (long)blockIdx.z * b_batch;
    float*       Cb = C + (long)blockIdx.z * c_batch;

    const int m0  = blockIdx.y * 64;
    const int n0  = blockIdx.x * 64;
    const int tid = threadIdx.x;
    const int tx  = tid & 15;   // n direction
    const int ty  = tid >> 4;   // m direction

    float acc[4][4] = {};

    for (int k0 = 0; k0 < K; k0 += 16) {
        #pragma unroll
        for (int i = 0; i < 4; i++) {
            int idx = tid + i * 256;
            int m, k;
            if (A_KCONTIG) { m = idx >> 4; k = idx & 15; }
            else           { k = idx >> 6; m = idx & 63; }
            As[k][m] = Ab[(long)(m0 + m) * lda_m + (long)(k0 + k) * lda_k];
        }
        #pragma unroll
        for (int i = 0; i < 4; i++) {
            int idx = tid + i * 256;
            int k, n;
            if (B_NCONTIG) { k = idx >> 6; n = idx & 63; }
            else           { n = idx >> 4; k = idx & 15; }
            Bs[k][n] = Bb[(long)(k0 + k) * ldb_k + (long)(n0 + n) * ldb_n];
        }
        __syncthreads();
        #pragma unroll
        for (int kk = 0; kk < 16; kk++) {
            float4 av = *(const float4*)&As[kk][4 * ty];
            float4 bv = *(const float4*)&Bs[kk][4 * tx];
            float a[4] = {av.x, av.y, av.z, av.w};
            float b[4] = {bv.x, bv.y, bv.z, bv.w};
            #pragma unroll
            for (int i = 0; i < 4; i++)
                #pragma unroll
                for (int j = 0; j < 4; j++)
                    acc[i][j] = fmaf(a[i], b[j], acc[i][j]);
        }
        __syncthreads();
    }

    #pragma unroll
    for (int i = 0; i < 4; i++) {
        int m = m0 + 4 * ty + i;
        float bval = BIAS ? bias[m] : 0.0f;
        float4 v;
        v.x = acc[i][0] + bval;
        v.y = acc[i][1] + bval;
        v.z = acc[i][2] + bval;
        v.w = acc[i][3] + bval;
        *(float4*)&Cb[(long)m * ldc + n0 + 4 * tx] = v;
    }
}

// ---------------- softmax over rows of length N_ (axis=2 of [B,M,N]) -----------
__global__ __launch_bounds__(256)
void softmax_rows(float* __restrict__ S)
{
    float* p = S + (long)blockIdx.x * N_;
    const int tid  = threadIdx.x;
    const int lane = tid & 31;
    const int wid  = tid >> 5;
    __shared__ float red[8];

    float v[16];
    float mx = -CUDART_INF_F;
    #pragma unroll
    for (int j = 0; j < 16; j++) { v[j] = p[tid + j * 256]; mx = fmaxf(mx, v[j]); }

    mx = warp_max(mx);
    if (lane == 0) red[wid] = mx;
    __syncthreads();
    #pragma unroll
    for (int i = 0; i < 8; i++) mx = fmaxf(mx, red[i]);

    float s = 0.f;
    #pragma unroll
    for (int j = 0; j < 16; j++) { v[j] = __expf(v[j] - mx); s += v[j]; }

    s = warp_sum(s);
    __syncthreads();
    if (lane == 0) red[wid] = s;
    __syncthreads();
    float tot = 0.f;
    #pragma unroll
    for (int i = 0; i < 8; i++) tot += red[i];
    float inv = 1.0f / tot;

    #pragma unroll
    for (int j = 0; j < 16; j++) p[tid + j * 256] = v[j] * inv;
}

// ---------------- softmax over m (axis=1 of [B,M,N], stride N_) -----------------
__global__ __launch_bounds__(256)
void softmax_cols(float* __restrict__ U)
{
    const int b = blockIdx.y;
    const int n = blockIdx.x * 256 + threadIdx.x;
    float* base = U + (long)b * M_ * N_ + n;

    float mx = -CUDART_INF_F, s = 0.f;
    #pragma unroll 4
    for (int m = 0; m < M_; m++) {
        float vv = base[(long)m * N_];
        float nm = fmaxf(mx, vv);
        s = s * __expf(mx - nm) + __expf(vv - nm);
        mx = nm;
    }
    float inv = 1.0f / s;
    #pragma unroll 4
    for (int m = 0; m < M_; m++) {
        long off = (long)m * N_;
        base[off] = __expf(base[off] - mx) * inv;
    }
}

// ---------------- BN stats per output channel o over (B, C) ---------------------
__global__ __launch_bounds__(256)
void bn_stats(const float* __restrict__ y, float* __restrict__ mu, float* __restrict__ istd)
{
    const int o = blockIdx.x;
    const int tid  = threadIdx.x;
    const int lane = tid & 31;
    const int wid  = tid >> 5;
    __shared__ float rs[8], rq[8];

    float s = 0.f, q = 0.f;
    for (int idx = tid; idx < B_ * C_; idx += 256) {
        int b = idx >> 7, c = idx & 127;
        float vv = y[(long)b * M_ * C_ + (long)o * C_ + c];
        s += vv; q += vv * vv;
    }
    s = warp_sum(s);
    q = warp_sum(q);
    if (lane == 0) { rs[wid] = s; rq[wid] = q; }
    __syncthreads();
    if (tid == 0) {
        float S = 0.f, Q = 0.f;
        #pragma unroll
        for (int i = 0; i < 8; i++) { S += rs[i]; Q += rq[i]; }
        float mean = S * (1.0f / (B_ * C_));
        float var  = Q * (1.0f / (B_ * C_)) - mean * mean;
        mu[o]   = mean;
        istd[o] = rsqrtf(var + EPSI);
    }
}

// ---------------- BN apply + residual + relu, updates h in place ----------------
__global__ __launch_bounds__(256)
void bn_apply(const float* __restrict__ y, float* __restrict__ h,
              const float* __restrict__ mu, const float* __restrict__ istd,
              const float* __restrict__ gamma, const float* __restrict__ beta)
{
    long i = (long)blockIdx.x * 256 + threadIdx.x;   // B*M*C = 2,097,152
    int o = (int)((i >> 7) & (M_ - 1));
    float yn = (y[i] - mu[o]) * istd[o] * gamma[o] + beta[o];
    h[i] = fmaxf(yn + h[i], 0.0f);
}

// ---------------- launch ---------------------------------------------------------
extern "C" void kernel_launch(void* const* d_in, const int* in_sizes, int n_in,
                              void* d_out, int out_size)
{
    const float* x        = (const float*)d_in[0];   // [B, C, N, 1]
    const float* W_pool   = (const float*)d_in[1];   // [M, C]
    const float* Wf       = (const float*)d_in[2];   // [L, M, M]
    const float* gamma    = (const float*)d_in[3];   // [L, M]
    const float* beta     = (const float*)d_in[4];   // [L, M]
    const float* W_unpool = (const float*)d_in[5];   // [M, C]
    const float* b_unpool = (const float*)d_in[6];   // [M]
    float*       out      = (float*)d_out;           // [B, C, N, 1]

    float *pS, *ph, *py, *pmu, *pistd;
    cudaGetSymbolAddress((void**)&pS,    g_S);
    cudaGetSymbolAddress((void**)&ph,    g_h);
    cudaGetSymbolAddress((void**)&py,    g_y);
    cudaGetSymbolAddress((void**)&pmu,   g_mu);
    cudaGetSymbolAddress((void**)&pistd, g_istd);

    const long MN = (long)M_ * N_;
    const long CN = (long)C_ * N_;
    const long MC = (long)M_ * C_;

    // 1) pool logits: S[b,m,n] = sum_c W_pool[m,c] * x[b,c,n]
    gemm64<true, true, false><<<dim3(N_ / 64, M_ / 64, B_), 256>>>(
        W_pool, x, pS, nullptr, C_,
        0, CN, MN, C_, 1, N_, 1, N_);

    // 2) softmax over n
    softmax_rows<<<B_ * M_, 256>>>(pS);

    // 3) pooled features: h[b,m,c] = sum_n S[b,m,n] * x[b,c,n]
    gemm64<true, false, false><<<dim3(C_ / 64, M_ / 64, B_), 256>>>(
        pS, x, ph, nullptr, N_,
        MN, CN, MC, N_, 1, 1, N_, C_);

    // 4) filtering layers
    for (int l = 0; l < L_; l++) {
        gemm64<true, true, false><<<dim3(C_ / 64, M_ / 64, B_), 256>>>(
            Wf + (long)l * M_ * M_, ph, py, nullptr, M_,
            0, MC, MC, M_, 1, C_, 1, C_);
        bn_stats<<<M_, 256>>>(py, pmu, pistd);
        bn_apply<<<(B_ * M_ * C_) / 256, 256>>>(py, ph, pmu, pistd,
                                                gamma + l * M_, beta + l * M_);
    }

    // 5) unpool logits: S[b,m,n] = sum_c W_unpool[m,c] * x[b,c,n] + b_unpool[m]
    gemm64<true, true, true><<<dim3(N_ / 64, M_ / 64, B_), 256>>>(
        W_unpool, x, pS, b_unpool, C_,
        0, CN, MN, C_, 1, N_, 1, N_);

    // 6) softmax over m
    softmax_cols<<<dim3(N_ / 256, B_), 256>>>(pS);

    // 7) output: out[b,c,n] = sum_m h[b,m,c] * S[b,m,n]
    gemm64<false, true, false><<<dim3(N_ / 64, C_ / 64, B_), 256>>>(
        ph, pS, out, nullptr, M_,
        MC, MN, CN, 1, C_, N_, 1, N_);
}